// round 1
// baseline (speedup 1.0000x reference)
#include <cuda_runtime.h>
#include <math.h>

#define B 2
#define NPROP 1000
#define NCLS 81
#define MASK_ELEMS (28*28*81)      // 63504 floats per proposal mask
#define MASK_V4 (MASK_ELEMS/4)     // 15876 float4
#define MAXI 100
#define NMS_THR 0.3f
#define MIN_CONF 0.5f

// ---------------- scratch (device globals; no allocation allowed) ------------
__device__ float        g_refined[B][NPROP][4];
__device__ float        g_score[B][NPROP];
__device__ int          g_cid[B][NPROP];
__device__ unsigned char g_keep0[B][NPROP];
__device__ unsigned char g_nms[B][NPROP];
__device__ int          g_slot[B][MAXI];
__device__ int          g_kcount[B];

// ---------------- stage 1: argmax + box refine + clip ------------------------
__global__ void prep_kernel(const float* __restrict__ rois,
                            const float* __restrict__ probs,
                            const float* __restrict__ deltas,
                            const float* __restrict__ window) {
    int idx = blockIdx.x * blockDim.x + threadIdx.x;
    if (idx >= B * NPROP) return;
    int b = idx / NPROP, i = idx % NPROP;

    const float* p = probs + (size_t)idx * NCLS;
    float best = p[0]; int cid = 0;
    for (int c = 1; c < NCLS; c++) {
        float v = p[c];
        if (v > best) { best = v; cid = c; }   // first-occurrence argmax (strict >)
    }

    const float* r = rois + (size_t)idx * 4;
    float r0 = r[0], r1 = r[1], r2 = r[2], r3 = r[3];
    bool valid = (fabsf(r0) + fabsf(r1) + fabsf(r2) + fabsf(r3)) > 0.0f;

    const float* dl = deltas + ((size_t)idx * NCLS + cid) * 4;
    float dy = dl[0] * 0.1f, dx = dl[1] * 0.1f;
    float dh = dl[2] * 0.2f, dw = dl[3] * 0.2f;

    float h = r2 - r0, w = r3 - r1;
    float cy = r0 + 0.5f * h + dy * h;
    float cx = r1 + 0.5f * w + dx * w;
    h = h * expf(dh);
    w = w * expf(dw);
    float y1 = cy - 0.5f * h, x1 = cx - 0.5f * w;
    float y2 = cy + 0.5f * h, x2 = cx + 0.5f * w;

    float wy1 = window[0], wx1 = window[1], wy2 = window[2], wx2 = window[3];
    y1 = fminf(fmaxf(y1, wy1), wy2);
    x1 = fminf(fmaxf(x1, wx1), wx2);
    y2 = fminf(fmaxf(y2, wy1), wy2);
    x2 = fminf(fmaxf(x2, wx1), wx2);

    g_refined[b][i][0] = y1; g_refined[b][i][1] = x1;
    g_refined[b][i][2] = y2; g_refined[b][i][3] = x2;
    g_score[b][i] = best;
    g_cid[b][i]   = cid;
    g_keep0[b][i] = (valid && cid > 0 && best >= MIN_CONF) ? 1 : 0;
    g_nms[b][i]   = 0;
}

// ---------------- stage 2: per-(batch,class) greedy NMS ----------------------
// Equivalent to the reference's 100-iteration argmax scan: process candidates
// in (score desc, index asc) order; keep iff IoU<=thr vs all previously-kept;
// cap kept at MAXI.
__global__ void nms_kernel() {
    int b = blockIdx.x / (NCLS - 1);
    int c = 1 + blockIdx.x % (NCLS - 1);

    __shared__ int   cnt;
    __shared__ int   cidx[NPROP];
    __shared__ float cs[NPROP];
    __shared__ short ord[NPROP];
    __shared__ float kb[MAXI][4];

    if (threadIdx.x == 0) cnt = 0;
    __syncthreads();

    for (int i = threadIdx.x; i < NPROP; i += blockDim.x) {
        if (g_keep0[b][i] && g_cid[b][i] == c) {
            int p = atomicAdd(&cnt, 1);
            cidx[p] = i;
            cs[p]   = g_score[b][i];
        }
    }
    __syncthreads();
    int k = cnt;

    // rank: score desc, index asc (stable like jnp.argmax tie-break)
    for (int a = threadIdx.x; a < k; a += blockDim.x) {
        float sa = cs[a]; int ia = cidx[a];
        int r = 0;
        for (int j = 0; j < k; j++) {
            float sj = cs[j];
            r += (sj > sa) || (sj == sa && cidx[j] < ia);
        }
        ord[r] = (short)a;
    }
    __syncthreads();

    if (threadIdx.x == 0) {
        int nk = 0;
        for (int r = 0; r < k && nk < MAXI; r++) {
            int a = ord[r];
            int i = cidx[a];
            float y1 = g_refined[b][i][0], x1 = g_refined[b][i][1];
            float y2 = g_refined[b][i][2], x2 = g_refined[b][i][3];
            float area = (y2 - y1) * (x2 - x1);
            bool sup = false;
            for (int t = 0; t < nk; t++) {
                float ky1 = kb[t][0], kx1 = kb[t][1], ky2 = kb[t][2], kx2 = kb[t][3];
                float iy1 = fmaxf(ky1, y1), ix1 = fmaxf(kx1, x1);
                float iy2 = fminf(ky2, y2), ix2 = fminf(kx2, x2);
                float inter = fmaxf(iy2 - iy1, 0.0f) * fmaxf(ix2 - ix1, 0.0f);
                float ka = (ky2 - ky1) * (kx2 - kx1);
                float iou = inter / (ka + area - inter + 1e-8f);
                if (iou > NMS_THR) { sup = true; break; }
            }
            if (!sup) {
                kb[nk][0] = y1; kb[nk][1] = x1; kb[nk][2] = y2; kb[nk][3] = x2;
                nk++;
                g_nms[b][i] = 1;
            }
        }
    }
}

// ---------------- stage 3: stable top-k slot assignment -----------------------
// Kept boxes: rank by (score desc, index asc) -> slots [0, kcount)
// Non-kept:   ascending index fill -> slots [kcount, 100)  (matches lax.top_k
// stable tie-break over the all-equal NEG values)
__global__ void topk_kernel() {
    int b = blockIdx.x;
    __shared__ float s_s[NPROP];
    __shared__ unsigned char s_f[NPROP];
    __shared__ int kc;
    if (threadIdx.x == 0) kc = 0;
    __syncthreads();

    int local = 0;
    for (int i = threadIdx.x; i < NPROP; i += blockDim.x) {
        unsigned char f = (g_keep0[b][i] && g_nms[b][i]) ? 1 : 0;
        s_f[i] = f;
        s_s[i] = g_score[b][i];
        local += f;
    }
    atomicAdd(&kc, local);
    __syncthreads();
    int kcc = min(kc, MAXI);

    for (int i = threadIdx.x; i < NPROP; i += blockDim.x) {
        if (s_f[i]) {
            float si = s_s[i];
            int r = 0;
            for (int j = 0; j < NPROP; j++)
                r += (s_f[j] && ((s_s[j] > si) || (s_s[j] == si && j < i))) ? 1 : 0;
            if (r < MAXI) g_slot[b][r] = i;
        } else {
            int r = 0;
            for (int j = 0; j < i; j++) r += (s_f[j] == 0) ? 1 : 0;
            int s = kcc + r;
            if (s < MAXI) g_slot[b][s] = i;
        }
    }
    if (threadIdx.x == 0) g_kcount[b] = kcc;
}

// ---------------- stage 4a: det rows [B,100,6] --------------------------------
__global__ void det_kernel(float* __restrict__ out) {
    int b = blockIdx.x, s = threadIdx.x;
    if (s >= MAXI) return;
    float* o = out + ((size_t)b * MAXI + s) * 6;
    if (s < g_kcount[b]) {
        int i = g_slot[b][s];
        o[0] = g_refined[b][i][0];
        o[1] = g_refined[b][i][1];
        o[2] = g_refined[b][i][2];
        o[3] = g_refined[b][i][3];
        o[4] = (float)g_cid[b][i];
        o[5] = g_score[b][i];
    } else {
        o[0] = 0.f; o[1] = 0.f; o[2] = 0.f; o[3] = 0.f; o[4] = 0.f; o[5] = 0.f;
    }
}

// ---------------- stage 4b: mask gather ---------------------------------------
// 4-D interpretation: out[b,s] = ok[s] ? masks[b, slot[s]] : 0
__global__ void mask4d_kernel(const float* __restrict__ masks, float* __restrict__ out) {
    long long e = (long long)blockIdx.x * blockDim.x + threadIdx.x;
    long long total = (long long)B * MAXI * MASK_V4;
    if (e >= total) return;
    int row = (int)(e / MASK_V4);
    int w   = (int)(e % MASK_V4);
    int b = row / MAXI, s = row % MAXI;
    float4 v = make_float4(0.f, 0.f, 0.f, 0.f);
    if (s < g_kcount[b]) {
        int i = g_slot[b][s];
        const float4* src = (const float4*)(masks + (size_t)(b * NPROP + i) * MASK_ELEMS);
        v = src[w];
    }
    float4* dst = (float4*)(out + (size_t)B * MAXI * 6);
    dst[e] = v;
}

// 5-D interpretation (reference's broadcast outer product):
// out[b,i,j] = (i < kcount[b]) ? masks[b, slot[j]] : 0     (slot[j] valid for ALL j)
__global__ void mask5d_kernel(const float* __restrict__ masks, float* __restrict__ out) {
    long long e = (long long)blockIdx.x * blockDim.x + threadIdx.x;
    long long total = (long long)B * MAXI * MAXI * MASK_V4;
    if (e >= total) return;
    int row = (int)(e / MASK_V4);          // 0 .. B*100*100-1
    int w   = (int)(e % MASK_V4);
    int b   = row / (MAXI * MAXI);
    int rem = row % (MAXI * MAXI);
    int i   = rem / MAXI;
    int j   = rem % MAXI;
    float4 v = make_float4(0.f, 0.f, 0.f, 0.f);
    if (i < g_kcount[b]) {
        int src_row = g_slot[b][j];
        const float4* src = (const float4*)(masks + (size_t)(b * NPROP + src_row) * MASK_ELEMS);
        v = src[w];
    }
    float4* dst = (float4*)(out + (size_t)B * MAXI * 6);
    dst[e] = v;
}

// ---------------- launch ------------------------------------------------------
extern "C" void kernel_launch(void* const* d_in, const int* in_sizes, int n_in,
                              void* d_out, int out_size) {
    const float* rois   = (const float*)d_in[0];
    const float* probs  = (const float*)d_in[1];
    const float* deltas = (const float*)d_in[2];
    const float* masks  = (const float*)d_in[3];
    const float* window = (const float*)d_in[4];
    float* out = (float*)d_out;

    prep_kernel<<<(B * NPROP + 255) / 256, 256>>>(rois, probs, deltas, window);
    nms_kernel<<<B * (NCLS - 1), 128>>>();
    topk_kernel<<<B, 256>>>();
    det_kernel<<<B, MAXI>>>(out);

    long long det_elems  = (long long)B * MAXI * 6;
    long long mask_elems = (long long)out_size - det_elems;
    long long rows = mask_elems / MASK_ELEMS;

    if (rows >= (long long)B * MAXI * MAXI) {
        long long total = (long long)B * MAXI * MAXI * MASK_V4;
        int grid = (int)((total + 255) / 256);
        mask5d_kernel<<<grid, 256>>>(masks, out);
    } else {
        long long total = (long long)B * MAXI * MASK_V4;
        int grid = (int)((total + 255) / 256);
        mask4d_kernel<<<grid, 256>>>(masks, out);
    }
}

// round 2
// speedup vs baseline: 1.1777x; 1.1777x over previous
#include <cuda_runtime.h>
#include <math.h>

#define B 2
#define NPROP 1000
#define NCLS 81
#define MASK_ELEMS (28*28*81)      // 63504 floats per proposal mask
#define MASK_V4 (MASK_ELEMS/4)     // 15876 float4
#define MAXI 100
#define NMS_THR 0.3f
#define MIN_CONF 0.5f

// ---------------- scratch (device globals; no allocation allowed) ------------
__device__ float        g_refined[B][NPROP][4];
__device__ float        g_score[B][NPROP];
__device__ int          g_cid[B][NPROP];
__device__ unsigned char g_keep0[B][NPROP];
__device__ unsigned char g_nms[B][NPROP];
__device__ int          g_slot[B][MAXI];
__device__ int          g_kcount[B];

// ---------------- stage 1: argmax + box refine + clip ------------------------
__global__ void prep_kernel(const float* __restrict__ rois,
                            const float* __restrict__ probs,
                            const float* __restrict__ deltas,
                            const float* __restrict__ window) {
    int idx = blockIdx.x * blockDim.x + threadIdx.x;
    if (idx >= B * NPROP) return;
    int b = idx / NPROP, i = idx % NPROP;

    const float* p = probs + (size_t)idx * NCLS;
    float best = p[0]; int cid = 0;
    for (int c = 1; c < NCLS; c++) {
        float v = p[c];
        if (v > best) { best = v; cid = c; }   // first-occurrence argmax (strict >)
    }

    const float* r = rois + (size_t)idx * 4;
    float r0 = r[0], r1 = r[1], r2 = r[2], r3 = r[3];
    bool valid = (fabsf(r0) + fabsf(r1) + fabsf(r2) + fabsf(r3)) > 0.0f;

    const float* dl = deltas + ((size_t)idx * NCLS + cid) * 4;
    float dy = dl[0] * 0.1f, dx = dl[1] * 0.1f;
    float dh = dl[2] * 0.2f, dw = dl[3] * 0.2f;

    float h = r2 - r0, w = r3 - r1;
    float cy = r0 + 0.5f * h + dy * h;
    float cx = r1 + 0.5f * w + dx * w;
    h = h * expf(dh);
    w = w * expf(dw);
    float y1 = cy - 0.5f * h, x1 = cx - 0.5f * w;
    float y2 = cy + 0.5f * h, x2 = cx + 0.5f * w;

    float wy1 = window[0], wx1 = window[1], wy2 = window[2], wx2 = window[3];
    y1 = fminf(fmaxf(y1, wy1), wy2);
    x1 = fminf(fmaxf(x1, wx1), wx2);
    y2 = fminf(fmaxf(y2, wy1), wy2);
    x2 = fminf(fmaxf(x2, wx1), wx2);

    g_refined[b][i][0] = y1; g_refined[b][i][1] = x1;
    g_refined[b][i][2] = y2; g_refined[b][i][3] = x2;
    g_score[b][i] = best;
    g_cid[b][i]   = cid;
    g_keep0[b][i] = (valid && cid > 0 && best >= MIN_CONF) ? 1 : 0;
    g_nms[b][i]   = 0;
}

// ---------------- stage 2: per-(batch,class) greedy NMS ----------------------
__global__ void nms_kernel() {
    int b = blockIdx.x / (NCLS - 1);
    int c = 1 + blockIdx.x % (NCLS - 1);

    __shared__ int   cnt;
    __shared__ int   cidx[NPROP];
    __shared__ float cs[NPROP];
    __shared__ short ord[NPROP];
    __shared__ float kb[MAXI][4];

    if (threadIdx.x == 0) cnt = 0;
    __syncthreads();

    for (int i = threadIdx.x; i < NPROP; i += blockDim.x) {
        if (g_keep0[b][i] && g_cid[b][i] == c) {
            int p = atomicAdd(&cnt, 1);
            cidx[p] = i;
            cs[p]   = g_score[b][i];
        }
    }
    __syncthreads();
    int k = cnt;

    // rank: score desc, index asc
    for (int a = threadIdx.x; a < k; a += blockDim.x) {
        float sa = cs[a]; int ia = cidx[a];
        int r = 0;
        for (int j = 0; j < k; j++) {
            float sj = cs[j];
            r += (sj > sa) || (sj == sa && cidx[j] < ia);
        }
        ord[r] = (short)a;
    }
    __syncthreads();

    if (threadIdx.x == 0) {
        int nk = 0;
        for (int r = 0; r < k && nk < MAXI; r++) {
            int a = ord[r];
            int i = cidx[a];
            float y1 = g_refined[b][i][0], x1 = g_refined[b][i][1];
            float y2 = g_refined[b][i][2], x2 = g_refined[b][i][3];
            float area = (y2 - y1) * (x2 - x1);
            bool sup = false;
            for (int t = 0; t < nk; t++) {
                float ky1 = kb[t][0], kx1 = kb[t][1], ky2 = kb[t][2], kx2 = kb[t][3];
                float iy1 = fmaxf(ky1, y1), ix1 = fmaxf(kx1, x1);
                float iy2 = fminf(ky2, y2), ix2 = fminf(kx2, x2);
                float inter = fmaxf(iy2 - iy1, 0.0f) * fmaxf(ix2 - ix1, 0.0f);
                float ka = (ky2 - ky1) * (kx2 - kx1);
                float iou = inter / (ka + area - inter + 1e-8f);
                if (iou > NMS_THR) { sup = true; break; }
            }
            if (!sup) {
                kb[nk][0] = y1; kb[nk][1] = x1; kb[nk][2] = y2; kb[nk][3] = x2;
                nk++;
                g_nms[b][i] = 1;
            }
        }
    }
}

// ---------------- stage 3: stable top-k slot assignment -----------------------
__global__ void topk_kernel() {
    int b = blockIdx.x;
    __shared__ float s_s[NPROP];
    __shared__ unsigned char s_f[NPROP];
    __shared__ int kc;
    if (threadIdx.x == 0) kc = 0;
    __syncthreads();

    int local = 0;
    for (int i = threadIdx.x; i < NPROP; i += blockDim.x) {
        unsigned char f = (g_keep0[b][i] && g_nms[b][i]) ? 1 : 0;
        s_f[i] = f;
        s_s[i] = g_score[b][i];
        local += f;
    }
    atomicAdd(&kc, local);
    __syncthreads();
    int kcc = min(kc, MAXI);

    for (int i = threadIdx.x; i < NPROP; i += blockDim.x) {
        if (s_f[i]) {
            float si = s_s[i];
            int r = 0;
            for (int j = 0; j < NPROP; j++)
                r += (s_f[j] && ((s_s[j] > si) || (s_s[j] == si && j < i))) ? 1 : 0;
            if (r < MAXI) g_slot[b][r] = i;
        } else {
            int r = 0;
            for (int j = 0; j < i; j++) r += (s_f[j] == 0) ? 1 : 0;
            int s = kcc + r;
            if (s < MAXI) g_slot[b][s] = i;
        }
    }
    if (threadIdx.x == 0) g_kcount[b] = kcc;
}

// ---------------- stage 4a: det rows [B,100,6] --------------------------------
__global__ void det_kernel(float* __restrict__ out) {
    int b = blockIdx.x, s = threadIdx.x;
    if (s >= MAXI) return;
    float* o = out + ((size_t)b * MAXI + s) * 6;
    if (s < g_kcount[b]) {
        int i = g_slot[b][s];
        o[0] = g_refined[b][i][0];
        o[1] = g_refined[b][i][1];
        o[2] = g_refined[b][i][2];
        o[3] = g_refined[b][i][3];
        o[4] = (float)g_cid[b][i];
        o[5] = g_score[b][i];
    } else {
        o[0] = 0.f; o[1] = 0.f; o[2] = 0.f; o[3] = 0.f; o[4] = 0.f; o[5] = 0.f;
    }
}

// ---------------- stage 4b: 5-D broadcast mask write --------------------------
// out[b,i,j,:] = (i < kcount[b]) ? masks[b, slot[j], :] : 0
// Block = (chunk, j, b). Load chunk of source mask ONCE into registers,
// replicate to all 100 i-destinations with streaming (evict-first) stores.
#define CHUNK_V4 1024          // float4 per block-chunk (256 thr x 4)
#define NCHUNK   16            // ceil(15876 / 1024)

__global__ __launch_bounds__(256) void mask5d_bcast_kernel(
        const float* __restrict__ masks, float* __restrict__ out) {
    int b = blockIdx.z;
    int j = blockIdx.y;
    int base = blockIdx.x * CHUNK_V4 + threadIdx.x;   // first float4 index

    int kc   = g_kcount[b];
    int slot = g_slot[b][j];

    const float4* src = (const float4*)(masks + (size_t)(b * NPROP + slot) * MASK_ELEMS);

    int   idx0 = base;
    int   idx1 = base + 256;
    int   idx2 = base + 512;
    int   idx3 = base + 768;
    bool  ok0 = idx0 < MASK_V4, ok1 = idx1 < MASK_V4;
    bool  ok2 = idx2 < MASK_V4, ok3 = idx3 < MASK_V4;

    const float4 z = make_float4(0.f, 0.f, 0.f, 0.f);
    float4 v0 = ok0 ? __ldg(&src[idx0]) : z;
    float4 v1 = ok1 ? __ldg(&src[idx1]) : z;
    float4 v2 = ok2 ? __ldg(&src[idx2]) : z;
    float4 v3 = ok3 ? __ldg(&src[idx3]) : z;

    // dst row (b, i, j): offset ((b*MAXI + i)*MAXI + j) * MASK_V4 float4
    float4* dst0 = (float4*)(out + (size_t)B * MAXI * 6)
                 + ((size_t)(b * MAXI) * MAXI + j) * MASK_V4;
    const size_t istride = (size_t)MAXI * MASK_V4;    // between consecutive i

    #pragma unroll 4
    for (int i = 0; i < MAXI; i++) {
        float4* d = dst0 + (size_t)i * istride;
        bool on = (i < kc);
        float4 w0 = on ? v0 : z, w1 = on ? v1 : z;
        float4 w2 = on ? v2 : z, w3 = on ? v3 : z;
        if (ok0) __stcs(&d[idx0], w0);
        if (ok1) __stcs(&d[idx1], w1);
        if (ok2) __stcs(&d[idx2], w2);
        if (ok3) __stcs(&d[idx3], w3);
    }
}

// ---------------- 4-D fallback (defensive) ------------------------------------
__global__ void mask4d_kernel(const float* __restrict__ masks, float* __restrict__ out) {
    long long e = (long long)blockIdx.x * blockDim.x + threadIdx.x;
    long long total = (long long)B * MAXI * MASK_V4;
    if (e >= total) return;
    int row = (int)(e / MASK_V4);
    int w   = (int)(e % MASK_V4);
    int b = row / MAXI, s = row % MAXI;
    float4 v = make_float4(0.f, 0.f, 0.f, 0.f);
    if (s < g_kcount[b]) {
        int i = g_slot[b][s];
        const float4* src = (const float4*)(masks + (size_t)(b * NPROP + i) * MASK_ELEMS);
        v = src[w];
    }
    float4* dst = (float4*)(out + (size_t)B * MAXI * 6);
    dst[e] = v;
}

// ---------------- launch ------------------------------------------------------
extern "C" void kernel_launch(void* const* d_in, const int* in_sizes, int n_in,
                              void* d_out, int out_size) {
    const float* rois   = (const float*)d_in[0];
    const float* probs  = (const float*)d_in[1];
    const float* deltas = (const float*)d_in[2];
    const float* masks  = (const float*)d_in[3];
    const float* window = (const float*)d_in[4];
    float* out = (float*)d_out;

    prep_kernel<<<(B * NPROP + 255) / 256, 256>>>(rois, probs, deltas, window);
    nms_kernel<<<B * (NCLS - 1), 128>>>();
    topk_kernel<<<B, 256>>>();
    det_kernel<<<B, MAXI>>>(out);

    long long det_elems  = (long long)B * MAXI * 6;
    long long mask_elems = (long long)out_size - det_elems;
    long long rows = mask_elems / MASK_ELEMS;

    if (rows >= (long long)B * MAXI * MAXI) {
        dim3 grid(NCHUNK, MAXI, B);
        mask5d_bcast_kernel<<<grid, 256>>>(masks, out);
    } else {
        long long total = (long long)B * MAXI * MASK_V4;
        int gridn = (int)((total + 255) / 256);
        mask4d_kernel<<<gridn, 256>>>(masks, out);
    }
}

// round 3
// speedup vs baseline: 1.2236x; 1.0390x over previous
#include <cuda_runtime.h>
#include <math.h>
#include <cstdint>

#define B 2
#define NPROP 1000
#define NCLS 81
#define MASK_ELEMS (28*28*81)      // 63504 floats per proposal mask
#define MASK_V4 (MASK_ELEMS/4)     // 15876 float4
#define MAXI 100
#define NMS_THR 0.3f
#define MIN_CONF 0.5f

// ---------------- scratch (device globals; no allocation allowed) ------------
__device__ float        g_refined[B][NPROP][4];
__device__ float        g_score[B][NPROP];
__device__ int          g_cid[B][NPROP];
__device__ unsigned char g_keep0[B][NPROP];
__device__ unsigned char g_nms[B][NPROP];
__device__ int          g_slot[B][MAXI];
__device__ int          g_kcount[B];

// ---------------- stage 1: argmax + box refine + clip ------------------------
__global__ void prep_kernel(const float* __restrict__ rois,
                            const float* __restrict__ probs,
                            const float* __restrict__ deltas,
                            const float* __restrict__ window) {
    int idx = blockIdx.x * blockDim.x + threadIdx.x;
    if (idx >= B * NPROP) return;
    int b = idx / NPROP, i = idx % NPROP;

    const float* p = probs + (size_t)idx * NCLS;
    float best = p[0]; int cid = 0;
    for (int c = 1; c < NCLS; c++) {
        float v = p[c];
        if (v > best) { best = v; cid = c; }   // first-occurrence argmax (strict >)
    }

    const float* r = rois + (size_t)idx * 4;
    float r0 = r[0], r1 = r[1], r2 = r[2], r3 = r[3];
    bool valid = (fabsf(r0) + fabsf(r1) + fabsf(r2) + fabsf(r3)) > 0.0f;

    const float* dl = deltas + ((size_t)idx * NCLS + cid) * 4;
    float dy = dl[0] * 0.1f, dx = dl[1] * 0.1f;
    float dh = dl[2] * 0.2f, dw = dl[3] * 0.2f;

    float h = r2 - r0, w = r3 - r1;
    float cy = r0 + 0.5f * h + dy * h;
    float cx = r1 + 0.5f * w + dx * w;
    h = h * expf(dh);
    w = w * expf(dw);
    float y1 = cy - 0.5f * h, x1 = cx - 0.5f * w;
    float y2 = cy + 0.5f * h, x2 = cx + 0.5f * w;

    float wy1 = window[0], wx1 = window[1], wy2 = window[2], wx2 = window[3];
    y1 = fminf(fmaxf(y1, wy1), wy2);
    x1 = fminf(fmaxf(x1, wx1), wx2);
    y2 = fminf(fmaxf(y2, wy1), wy2);
    x2 = fminf(fmaxf(x2, wx1), wx2);

    g_refined[b][i][0] = y1; g_refined[b][i][1] = x1;
    g_refined[b][i][2] = y2; g_refined[b][i][3] = x2;
    g_score[b][i] = best;
    g_cid[b][i]   = cid;
    g_keep0[b][i] = (valid && cid > 0 && best >= MIN_CONF) ? 1 : 0;
    g_nms[b][i]   = 0;
}

// ---------------- stage 2: per-(batch,class) greedy NMS ----------------------
__global__ void nms_kernel() {
    int b = blockIdx.x / (NCLS - 1);
    int c = 1 + blockIdx.x % (NCLS - 1);

    __shared__ int   cnt;
    __shared__ int   cidx[NPROP];
    __shared__ float cs[NPROP];
    __shared__ short ord[NPROP];
    __shared__ float kb[MAXI][4];

    if (threadIdx.x == 0) cnt = 0;
    __syncthreads();

    for (int i = threadIdx.x; i < NPROP; i += blockDim.x) {
        if (g_keep0[b][i] && g_cid[b][i] == c) {
            int p = atomicAdd(&cnt, 1);
            cidx[p] = i;
            cs[p]   = g_score[b][i];
        }
    }
    __syncthreads();
    int k = cnt;

    // rank: score desc, index asc (stable argmax tie-break)
    for (int a = threadIdx.x; a < k; a += blockDim.x) {
        float sa = cs[a]; int ia = cidx[a];
        int r = 0;
        for (int j = 0; j < k; j++) {
            float sj = cs[j];
            r += (sj > sa) || (sj == sa && cidx[j] < ia);
        }
        ord[r] = (short)a;
    }
    __syncthreads();

    if (threadIdx.x == 0) {
        int nk = 0;
        for (int r = 0; r < k && nk < MAXI; r++) {
            int a = ord[r];
            int i = cidx[a];
            float y1 = g_refined[b][i][0], x1 = g_refined[b][i][1];
            float y2 = g_refined[b][i][2], x2 = g_refined[b][i][3];
            float area = (y2 - y1) * (x2 - x1);
            bool sup = false;
            for (int t = 0; t < nk; t++) {
                float ky1 = kb[t][0], kx1 = kb[t][1], ky2 = kb[t][2], kx2 = kb[t][3];
                float iy1 = fmaxf(ky1, y1), ix1 = fmaxf(kx1, x1);
                float iy2 = fminf(ky2, y2), ix2 = fminf(kx2, x2);
                float inter = fmaxf(iy2 - iy1, 0.0f) * fmaxf(ix2 - ix1, 0.0f);
                float ka = (ky2 - ky1) * (kx2 - kx1);
                float iou = inter / (ka + area - inter + 1e-8f);
                if (iou > NMS_THR) { sup = true; break; }
            }
            if (!sup) {
                kb[nk][0] = y1; kb[nk][1] = x1; kb[nk][2] = y2; kb[nk][3] = x2;
                nk++;
                g_nms[b][i] = 1;
            }
        }
    }
}

// ---------------- stage 3: stable top-k + det rows (fused) --------------------
__global__ void topk_det_kernel(float* __restrict__ out) {
    int b = blockIdx.x;
    __shared__ float s_s[NPROP];
    __shared__ unsigned char s_f[NPROP];
    __shared__ int s_slot[MAXI];
    __shared__ int kc;
    if (threadIdx.x == 0) kc = 0;
    __syncthreads();

    int local = 0;
    for (int i = threadIdx.x; i < NPROP; i += blockDim.x) {
        unsigned char f = (g_keep0[b][i] && g_nms[b][i]) ? 1 : 0;
        s_f[i] = f;
        s_s[i] = g_score[b][i];
        local += f;
    }
    atomicAdd(&kc, local);
    __syncthreads();
    int kcc = min(kc, MAXI);

    for (int i = threadIdx.x; i < NPROP; i += blockDim.x) {
        if (s_f[i]) {
            float si = s_s[i];
            int r = 0;
            for (int j = 0; j < NPROP; j++)
                r += (s_f[j] && ((s_s[j] > si) || (s_s[j] == si && j < i))) ? 1 : 0;
            if (r < MAXI) s_slot[r] = i;
        } else {
            int r = 0;
            for (int j = 0; j < i; j++) r += (s_f[j] == 0) ? 1 : 0;
            int s = kcc + r;
            if (s < MAXI) s_slot[s] = i;
        }
    }
    __syncthreads();

    // publish slots + kcount
    if (threadIdx.x < MAXI) g_slot[b][threadIdx.x] = s_slot[threadIdx.x];
    if (threadIdx.x == 0) g_kcount[b] = kcc;

    // det rows [B,100,6]
    int s = threadIdx.x;
    if (s < MAXI) {
        float* o = out + ((size_t)b * MAXI + s) * 6;
        if (s < kcc) {
            int i = s_slot[s];
            o[0] = g_refined[b][i][0];
            o[1] = g_refined[b][i][1];
            o[2] = g_refined[b][i][2];
            o[3] = g_refined[b][i][3];
            o[4] = (float)g_cid[b][i];
            o[5] = s_s[i];
        } else {
            o[0] = 0.f; o[1] = 0.f; o[2] = 0.f; o[3] = 0.f; o[4] = 0.f; o[5] = 0.f;
        }
    }
}

// ---------------- stage 4: 5-D broadcast mask write via TMA bulk stores -------
// out[b,i,j,:] = (i < kcount[b]) ? masks[b, slot[j], :] : 0
// Block = (chunk, j, b). Stage chunk in SMEM once; issue 100 cp.async.bulk
// SMEM->GMEM stores (one per i). Zero SMEM buffer serves i >= kcount rows.
#define CHUNK_V4 1024          // float4 per block-chunk
#define NCHUNK   16            // ceil(15876 / 1024)

__device__ __forceinline__ uint32_t smem_u32(const void* p) {
    uint32_t a;
    asm("{ .reg .u64 t; cvta.to.shared.u64 t, %1; cvt.u32.u64 %0, t; }"
        : "=r"(a) : "l"(p));
    return a;
}

__global__ __launch_bounds__(256) void mask5d_tma_kernel(
        const float* __restrict__ masks, float* __restrict__ out) {
    __shared__ alignas(128) float4 s_data[CHUNK_V4];
    __shared__ alignas(128) float4 s_zero[CHUNK_V4];

    int b = blockIdx.z;
    int j = blockIdx.y;
    int chunk0 = blockIdx.x * CHUNK_V4;
    int n_v4 = MASK_V4 - chunk0; if (n_v4 > CHUNK_V4) n_v4 = CHUNK_V4;

    int kc   = g_kcount[b];
    int slot = g_slot[b][j];

    const float4* src = (const float4*)(masks + (size_t)(b * NPROP + slot) * MASK_ELEMS)
                        + chunk0;
    const float4 z = make_float4(0.f, 0.f, 0.f, 0.f);
    for (int t = threadIdx.x; t < n_v4; t += 256) {
        s_data[t] = __ldg(&src[t]);
        s_zero[t] = z;
    }
    __syncthreads();
    asm volatile("fence.proxy.async.shared::cta;" ::: "memory");

    if (threadIdx.x == 0) {
        uint32_t sa_data = smem_u32(s_data);
        uint32_t sa_zero = smem_u32(s_zero);
        // dst row (b, i, j): ((b*MAXI + i)*MAXI + j) * MASK_V4 float4
        char* dst = (char*)((float4*)(out + (size_t)B * MAXI * 6)
                    + ((size_t)(b * MAXI) * MAXI + j) * MASK_V4 + chunk0);
        const size_t istride = (size_t)MAXI * MASK_V4 * 16;
        const int bytes = n_v4 * 16;

        int i = 0;
        for (; i < kc; i++) {
            asm volatile(
                "cp.async.bulk.global.shared::cta.bulk_group [%0], [%1], %2;"
                :: "l"(dst), "r"(sa_data), "r"(bytes) : "memory");
            dst += istride;
        }
        for (; i < MAXI; i++) {
            asm volatile(
                "cp.async.bulk.global.shared::cta.bulk_group [%0], [%1], %2;"
                :: "l"(dst), "r"(sa_zero), "r"(bytes) : "memory");
            dst += istride;
        }
        asm volatile("cp.async.bulk.commit_group;" ::: "memory");
        asm volatile("cp.async.bulk.wait_group 0;" ::: "memory");
    }
    __syncthreads();   // SMEM must stay alive until TMA reads complete
}

// ---------------- 4-D fallback (defensive) ------------------------------------
__global__ void mask4d_kernel(const float* __restrict__ masks, float* __restrict__ out) {
    long long e = (long long)blockIdx.x * blockDim.x + threadIdx.x;
    long long total = (long long)B * MAXI * MASK_V4;
    if (e >= total) return;
    int row = (int)(e / MASK_V4);
    int w   = (int)(e % MASK_V4);
    int b = row / MAXI, s = row % MAXI;
    float4 v = make_float4(0.f, 0.f, 0.f, 0.f);
    if (s < g_kcount[b]) {
        int i = g_slot[b][s];
        const float4* src = (const float4*)(masks + (size_t)(b * NPROP + i) * MASK_ELEMS);
        v = src[w];
    }
    float4* dst = (float4*)(out + (size_t)B * MAXI * 6);
    dst[e] = v;
}

// ---------------- launch ------------------------------------------------------
extern "C" void kernel_launch(void* const* d_in, const int* in_sizes, int n_in,
                              void* d_out, int out_size) {
    const float* rois   = (const float*)d_in[0];
    const float* probs  = (const float*)d_in[1];
    const float* deltas = (const float*)d_in[2];
    const float* masks  = (const float*)d_in[3];
    const float* window = (const float*)d_in[4];
    float* out = (float*)d_out;

    prep_kernel<<<(B * NPROP + 255) / 256, 256>>>(rois, probs, deltas, window);
    nms_kernel<<<B * (NCLS - 1), 128>>>();
    topk_det_kernel<<<B, 256>>>(out);

    long long det_elems  = (long long)B * MAXI * 6;
    long long mask_elems = (long long)out_size - det_elems;
    long long rows = mask_elems / MASK_ELEMS;

    if (rows >= (long long)B * MAXI * MAXI) {
        dim3 grid(NCHUNK, MAXI, B);
        mask5d_tma_kernel<<<grid, 256>>>(masks, out);
    } else {
        long long total = (long long)B * MAXI * MASK_V4;
        int gridn = (int)((total + 255) / 256);
        mask4d_kernel<<<gridn, 256>>>(masks, out);
    }
}